// round 11
// baseline (speedup 1.0000x reference)
#include <cuda_runtime.h>

// 3-level db4 wavelet front-end. R7: each row split across TWO 256-thread CTAs
// (left half / right half with halo recompute). 4 phases / 3 barriers,
// register-fused synthesis, 25KB smem arena -> 7 CTAs/SM (56 warps).

#define NT 256
#define NROWS 2048
#define LEN0 8192
#define LEN1 4100
#define LEN2 2054
#define LEN3 1031

// ---- per-CTA local buffers (floats), offsets 16B-aligned ----
// A1[0,2080) D1[2080,4160) A2[4160,5208) D2[5208,6256)
// After Ph2, D1 region is reused: A3[2080,2608) D3[2608,3136)
#define OFF_A1 0
#define OFF_D1 2080
#define OFF_A3 2080
#define OFF_D3 2608
#define OFF_A2 4160
#define OFF_D2 5208
#define ARENA  6256

__constant__ float c_dec_lo[8] = {
    -0.0105974018f, 0.0328830117f, 0.0308413818f, -0.1870348117f,
    -0.0279837694f, 0.6308807679f, 0.7148465706f, 0.2303778133f};
__constant__ float c_dec_hi[8] = {
    -0.2303778133f, 0.7148465706f, -0.6308807679f, -0.0279837694f,
     0.1870348117f, 0.0308413818f, -0.0328830117f, -0.0105974018f};

// Synthesis polyphase taps (transpose conv, crop 7, T = 2L-8):
//   out[2u]   = e0*a[u]   + e1*a[u+1] + e2*a[u+2] + e3*a[u+3]
//   out[2u+1] = o0*a[u+1] + o1*a[u+2] + o2*a[u+3] + o3*a[u+4]
__constant__ float c_lo_e[4] = {-0.0105974018f, 0.0308413818f, -0.0279837694f, 0.7148465706f};
__constant__ float c_lo_o[4] = { 0.0328830117f, -0.1870348117f, 0.6308807679f, 0.2303778133f};
__constant__ float c_hi_e[4] = {-0.2303778133f, -0.6308807679f, 0.1870348117f, -0.0328830117f};
__constant__ float c_hi_o[4] = { 0.7148465706f, -0.0279837694f, 0.0308413818f, -0.0105974018f};

// ---- analysis chunk (4 outputs, global chunk index j) from gmem input ----
__device__ __forceinline__ void analysis_chunk_g(const float* __restrict__ xg,
                                                 float* __restrict__ lo,
                                                 float* __restrict__ hi,
                                                 int j, int bout) {
    if (j >= 1 && j <= 1023) {
        const float4* in4 = reinterpret_cast<const float4*>(xg) + (2 * j - 2);
        float v[16];
#pragma unroll
        for (int q = 0; q < 4; q++) {
            float4 t = in4[q];
            v[4 * q] = t.x; v[4 * q + 1] = t.y; v[4 * q + 2] = t.z; v[4 * q + 3] = t.w;
        }
        float slo[4], shi[4];
#pragma unroll
        for (int m = 0; m < 4; m++) {
            float sl = 0.f, sh = 0.f;
#pragma unroll
            for (int k = 0; k < 8; k++) {
                float xv = v[2 * m + 1 + k];
                sl = fmaf(xv, c_dec_lo[k], sl);
                sh = fmaf(xv, c_dec_hi[k], sh);
            }
            slo[m] = sl; shi[m] = sh;
        }
        int fb = (4 * j - bout) >> 2;
        reinterpret_cast<float4*>(lo)[fb] = make_float4(slo[0], slo[1], slo[2], slo[3]);
        reinterpret_cast<float4*>(hi)[fb] = make_float4(shi[0], shi[1], shi[2], shi[3]);
    } else {
#pragma unroll
        for (int m = 0; m < 4; m++) {
            int o = 4 * j + m;
            if (o >= LEN1) break;
            int base = 2 * o - 7;
            float sl = 0.f, sh = 0.f;
#pragma unroll
            for (int k = 0; k < 8; k++) {
                int i = base + k;
                i = i < 0 ? -i : i;
                i = min(i, 2 * LEN0 - 2 - i);
                float xv = xg[i];
                sl = fmaf(xv, c_dec_lo[k], sl);
                sh = fmaf(xv, c_dec_hi[k], sh);
            }
            lo[o - bout] = sl;
            hi[o - bout] = sh;
        }
    }
}

// ---- analysis chunk (4 outputs, global chunk index j) from smem (based) ----
__device__ __forceinline__ void analysis_chunk_s(const float* __restrict__ in, int bin, int L,
                                                 float* __restrict__ lo,
                                                 float* __restrict__ hi, int bout, int Lout,
                                                 int j) {
    const int jhi = (L - 8) >> 3;
    if (j >= 1 && j <= jhi) {
        const float4* in4 = reinterpret_cast<const float4*>(in) + ((8 * j - 8 - bin) >> 2);
        float v[16];
#pragma unroll
        for (int q = 0; q < 4; q++) {
            float4 t = in4[q];
            v[4 * q] = t.x; v[4 * q + 1] = t.y; v[4 * q + 2] = t.z; v[4 * q + 3] = t.w;
        }
        float slo[4], shi[4];
#pragma unroll
        for (int m = 0; m < 4; m++) {
            float sl = 0.f, sh = 0.f;
#pragma unroll
            for (int k = 0; k < 8; k++) {
                float xv = v[2 * m + 1 + k];
                sl = fmaf(xv, c_dec_lo[k], sl);
                sh = fmaf(xv, c_dec_hi[k], sh);
            }
            slo[m] = sl; shi[m] = sh;
        }
        int fb = (4 * j - bout) >> 2;
        reinterpret_cast<float4*>(lo)[fb] = make_float4(slo[0], slo[1], slo[2], slo[3]);
        reinterpret_cast<float4*>(hi)[fb] = make_float4(shi[0], shi[1], shi[2], shi[3]);
    } else {
        const int twoLm2 = 2 * L - 2;
#pragma unroll
        for (int m = 0; m < 4; m++) {
            int o = 4 * j + m;
            if (o >= Lout) break;
            int base = 2 * o - 7;
            float sl = 0.f, sh = 0.f;
#pragma unroll
            for (int k = 0; k < 8; k++) {
                int i = base + k;
                i = i < 0 ? -i : i;
                i = min(i, twoLm2 - i);
                float xv = in[i - bin];
                sl = fmaf(xv, c_dec_lo[k], sl);
                sh = fmaf(xv, c_dec_hi[k], sh);
            }
            lo[o - bout] = sl;
            hi[o - bout] = sh;
        }
    }
}

// ---- single-stage synth, 8 pairs/chunk (global chunk j), input based ----
__device__ __forceinline__ void synth8_chunk(const float* __restrict__ a, int bin,
                                             const float* __restrict__ wE,
                                             const float* __restrict__ wO,
                                             float* __restrict__ outg, int j) {
    const float e0 = wE[0], e1 = wE[1], e2 = wE[2], e3 = wE[3];
    const float o0 = wO[0], o1 = wO[1], o2 = wO[2], o3 = wO[3];
    const float4* a4 = reinterpret_cast<const float4*>(a) + ((8 * j - bin) >> 2);
    float4 A = a4[0], B = a4[1], C = a4[2];
    float v[12] = {A.x, A.y, A.z, A.w, B.x, B.y, B.z, B.w, C.x, C.y, C.z, C.w};
    float4* o4 = reinterpret_cast<float4*>(outg + 16 * j);
#pragma unroll
    for (int h = 0; h < 2; h++) {
        float r[8];
#pragma unroll
        for (int m = 0; m < 4; m++) {
            int t = 4 * h + m;
            r[2 * m]     = fmaf(e0, v[t],     fmaf(e1, v[t + 1], fmaf(e2, v[t + 2], e3 * v[t + 3])));
            r[2 * m + 1] = fmaf(o0, v[t + 1], fmaf(o1, v[t + 2], fmaf(o2, v[t + 3], o3 * v[t + 4])));
        }
        o4[2 * h]     = make_float4(r[0], r[1], r[2], r[3]);
        o4[2 * h + 1] = make_float4(r[4], r[5], r[6], r[7]);
    }
}

// ---- double-fused synth: b(2054-level) ->hi-> 4100 ->lo-> 8192, chunk j ----
__device__ __forceinline__ void synth2_chunk(const float* __restrict__ b, int bin,
                                             float* __restrict__ outg, int j) {
    const float a0 = c_hi_e[0], a1 = c_hi_e[1], a2 = c_hi_e[2], a3 = c_hi_e[3];
    const float p0 = c_hi_o[0], p1 = c_hi_o[1], p2 = c_hi_o[2], p3 = c_hi_o[3];
    const float e0 = c_lo_e[0], e1 = c_lo_e[1], e2 = c_lo_e[2], e3 = c_lo_e[3];
    const float o0 = c_lo_o[0], o1 = c_lo_o[1], o2 = c_lo_o[2], o3 = c_lo_o[3];
    const float4* b4 = reinterpret_cast<const float4*>(b) + ((4 * j - bin) >> 2);
    float4 B0 = b4[0], B1 = b4[1], B2 = b4[2];
    float bl[12] = {B0.x, B0.y, B0.z, B0.w, B1.x, B1.y, B1.z, B1.w,
                    B2.x, B2.y, B2.z, B2.w};
    float mid[12];
#pragma unroll
    for (int g = 0; g < 6; g++) {
        mid[2 * g]     = fmaf(a0, bl[g],     fmaf(a1, bl[g + 1], fmaf(a2, bl[g + 2], a3 * bl[g + 3])));
        mid[2 * g + 1] = fmaf(p0, bl[g + 1], fmaf(p1, bl[g + 2], fmaf(p2, bl[g + 3], p3 * bl[g + 4])));
    }
    float4* o4 = reinterpret_cast<float4*>(outg + 16 * j);
#pragma unroll
    for (int h = 0; h < 2; h++) {
        float r[8];
#pragma unroll
        for (int m = 0; m < 4; m++) {
            int t = 4 * h + m;
            r[2 * m]     = fmaf(e0, mid[t],     fmaf(e1, mid[t + 1], fmaf(e2, mid[t + 2], e3 * mid[t + 3])));
            r[2 * m + 1] = fmaf(o0, mid[t + 1], fmaf(o1, mid[t + 2], fmaf(o2, mid[t + 3], o3 * mid[t + 4])));
        }
        o4[2 * h]     = make_float4(r[0], r[1], r[2], r[3]);
        o4[2 * h + 1] = make_float4(r[4], r[5], r[6], r[7]);
    }
}

// ---- triple-fused synth: b(1031) ->A-> 2054 ->lo-> 4100 ->lo-> 8192 ----
__device__ __forceinline__ void synth3_chunk(const float* __restrict__ b, int bin,
                                             const float* __restrict__ wAe,
                                             const float* __restrict__ wAo,
                                             float* __restrict__ outg, int j) {
    const float a0 = wAe[0], a1 = wAe[1], a2 = wAe[2], a3 = wAe[3];
    const float p0 = wAo[0], p1 = wAo[1], p2 = wAo[2], p3 = wAo[3];
    const float e0 = c_lo_e[0], e1 = c_lo_e[1], e2 = c_lo_e[2], e3 = c_lo_e[3];
    const float o0 = c_lo_o[0], o1 = c_lo_o[1], o2 = c_lo_o[2], o3 = c_lo_o[3];
    float bl[10];
    const float2* b2 = reinterpret_cast<const float2*>(b) + ((2 * j - bin) >> 1);
#pragma unroll
    for (int q = 0; q < 5; q++) { float2 t = b2[q]; bl[2 * q] = t.x; bl[2 * q + 1] = t.y; }
    float m1[10];
#pragma unroll
    for (int v = 0; v < 5; v++) {
        m1[2 * v]     = fmaf(a0, bl[v],     fmaf(a1, bl[v + 1], fmaf(a2, bl[v + 2], a3 * bl[v + 3])));
        m1[2 * v + 1] = fmaf(p0, bl[v + 1], fmaf(p1, bl[v + 2], fmaf(p2, bl[v + 3], p3 * bl[v + 4])));
    }
    float m2[12];
#pragma unroll
    for (int w = 0; w < 6; w++) {
        m2[2 * w]     = fmaf(e0, m1[w],     fmaf(e1, m1[w + 1], fmaf(e2, m1[w + 2], e3 * m1[w + 3])));
        m2[2 * w + 1] = fmaf(o0, m1[w + 1], fmaf(o1, m1[w + 2], fmaf(o2, m1[w + 3], o3 * m1[w + 4])));
    }
    float4* o4 = reinterpret_cast<float4*>(outg + 16 * j);
#pragma unroll
    for (int h = 0; h < 2; h++) {
        float r[8];
#pragma unroll
        for (int m = 0; m < 4; m++) {
            int t = 4 * h + m;
            r[2 * m]     = fmaf(e0, m2[t],     fmaf(e1, m2[t + 1], fmaf(e2, m2[t + 2], e3 * m2[t + 3])));
            r[2 * m + 1] = fmaf(o0, m2[t + 1], fmaf(o1, m2[t + 2], fmaf(o2, m2[t + 3], o3 * m2[t + 4])));
        }
        o4[2 * h]     = make_float4(r[0], r[1], r[2], r[3]);
        o4[2 * h + 1] = make_float4(r[4], r[5], r[6], r[7]);
    }
}

__global__ void __launch_bounds__(NT, 7)
dwt_frontend_kernel(const float* __restrict__ x, float* __restrict__ out) {
    extern __shared__ float s[];
    const int tid = threadIdx.x;
    const int half = blockIdx.x & 1;
    const int row = blockIdx.x >> 1;
    const float* xg = x + (size_t)row * LEN0;
    const size_t bstride = (size_t)NROWS * LEN0;
    float* ob = out + (size_t)row * LEN0;

    // Global base index of this CTA's local slice at each level.
    const int B1 = half ? 2024 : 0;   // A1/D1 covers [B1, B1+2080)
    const int B2 = half ? 1016 : 0;   // A2/D2 covers [B2, B2+1048)
    const int B3 = half ? 512  : 0;   // A3/D3 covers [B3, B3+528)
    const int JS = half ? 256  : 0;   // synth chunk base (256 chunks per half)

    // ---- Ph1: analysis L1 from gmem ----
    {
        const int j0 = half ? 506 : 0;
        const int n  = half ? 519 : 520;
        for (int t = tid; t < n; t += NT)
            analysis_chunk_g(xg, s + OFF_A1, s + OFF_D1, j0 + t, B1);
    }
    __syncthreads();

    // ---- Ph2: analysis L2 (260) + band3 synth (256) ----
    {
        const int j0a = half ? 254 : 0;
        for (int t = tid; t < 516; t += NT) {
            if (t < 260)
                analysis_chunk_s(s + OFF_A1, B1, LEN1, s + OFF_A2, s + OFF_D2, B2, LEN2, j0a + t);
            else
                synth8_chunk(s + OFF_D1, B1, c_hi_e, c_hi_o, ob + 3 * bstride, JS + (t - 260));
        }
    }
    __syncthreads();

    // ---- Ph3: analysis L3 (130) + band2 double-fused synth (256) ----
    // (A3/D3 land in the dead D1 region.)
    {
        const int j0a = half ? 128 : 0;
        for (int t = tid; t < 386; t += NT) {
            if (t < 130)
                analysis_chunk_s(s + OFF_A2, B2, LEN2, s + OFF_A3, s + OFF_D3, B3, LEN3, j0a + t);
            else
                synth2_chunk(s + OFF_D2, B2, ob + 2 * bstride, JS + (t - 130));
        }
    }
    __syncthreads();

    // ---- Ph4: bands 1 and 0, triple-fused synth (256 + 256) ----
    for (int t = tid; t < 512; t += NT) {
        if (t < 256)
            synth3_chunk(s + OFF_D3, B3, c_hi_e, c_hi_o, ob + 1 * bstride, JS + t);
        else
            synth3_chunk(s + OFF_A3, B3, c_lo_e, c_lo_o, ob, JS + (t - 256));
    }
}

extern "C" void kernel_launch(void* const* d_in, const int* in_sizes, int n_in,
                              void* d_out, int out_size) {
    const float* x = (const float*)d_in[0];
    float* out = (float*)d_out;
    const size_t smem = (size_t)ARENA * sizeof(float);   // 25024 B -> 7 CTAs/SM
    cudaFuncSetAttribute(dwt_frontend_kernel,
                         cudaFuncAttributeMaxDynamicSharedMemorySize, (int)smem);
    dwt_frontend_kernel<<<2 * NROWS, NT, smem>>>(x, out);
}

// round 13
// speedup vs baseline: 1.2267x; 1.2267x over previous
#include <cuda_runtime.h>

// 3-level db4 wavelet front-end. R8: row split across two 256-thread CTAs
// (halo recompute) + float4-per-thread synthesis for fully coalesced STG.
// 4 phases / 3 barriers, 25KB smem arena.

#define NT 256
#define NROWS 2048
#define LEN0 8192
#define LEN1 4100
#define LEN2 2054
#define LEN3 1031

// ---- per-CTA local buffers (floats), offsets 16B-aligned ----
// A1[0,2080) D1[2080,4160) A2[4160,5208) D2[5208,6256)
// After Ph2, D1 region reused: A3[2080,2608) D3[2608,3136)
#define OFF_A1 0
#define OFF_D1 2080
#define OFF_A3 2080
#define OFF_D3 2608
#define OFF_A2 4160
#define OFF_D2 5208
#define ARENA  6256

__constant__ float c_dec_lo[8] = {
    -0.0105974018f, 0.0328830117f, 0.0308413818f, -0.1870348117f,
    -0.0279837694f, 0.6308807679f, 0.7148465706f, 0.2303778133f};
__constant__ float c_dec_hi[8] = {
    -0.2303778133f, 0.7148465706f, -0.6308807679f, -0.0279837694f,
     0.1870348117f, 0.0308413818f, -0.0328830117f, -0.0105974018f};

// Synthesis polyphase taps (transpose conv, crop 7, T = 2L-8):
//   out[2u]   = e0*a[u]   + e1*a[u+1] + e2*a[u+2] + e3*a[u+3]
//   out[2u+1] = o0*a[u+1] + o1*a[u+2] + o2*a[u+3] + o3*a[u+4]
__constant__ float c_lo_e[4] = {-0.0105974018f, 0.0308413818f, -0.0279837694f, 0.7148465706f};
__constant__ float c_lo_o[4] = { 0.0328830117f, -0.1870348117f, 0.6308807679f, 0.2303778133f};
__constant__ float c_hi_e[4] = {-0.2303778133f, -0.6308807679f, 0.1870348117f, -0.0328830117f};
__constant__ float c_hi_o[4] = { 0.7148465706f, -0.0279837694f, 0.0308413818f, -0.0105974018f};

// ---- analysis chunk (4 outputs, global chunk index j) from gmem input ----
__device__ __forceinline__ void analysis_chunk_g(const float* __restrict__ xg,
                                                 float* __restrict__ lo,
                                                 float* __restrict__ hi,
                                                 int j, int bout) {
    if (j >= 1 && j <= 1023) {
        const float4* in4 = reinterpret_cast<const float4*>(xg) + (2 * j - 2);
        float v[16];
#pragma unroll
        for (int q = 0; q < 4; q++) {
            float4 t = in4[q];
            v[4 * q] = t.x; v[4 * q + 1] = t.y; v[4 * q + 2] = t.z; v[4 * q + 3] = t.w;
        }
        float slo[4], shi[4];
#pragma unroll
        for (int m = 0; m < 4; m++) {
            float sl = 0.f, sh = 0.f;
#pragma unroll
            for (int k = 0; k < 8; k++) {
                float xv = v[2 * m + 1 + k];
                sl = fmaf(xv, c_dec_lo[k], sl);
                sh = fmaf(xv, c_dec_hi[k], sh);
            }
            slo[m] = sl; shi[m] = sh;
        }
        int fb = (4 * j - bout) >> 2;
        reinterpret_cast<float4*>(lo)[fb] = make_float4(slo[0], slo[1], slo[2], slo[3]);
        reinterpret_cast<float4*>(hi)[fb] = make_float4(shi[0], shi[1], shi[2], shi[3]);
    } else {
#pragma unroll
        for (int m = 0; m < 4; m++) {
            int o = 4 * j + m;
            if (o >= LEN1) break;
            int base = 2 * o - 7;
            float sl = 0.f, sh = 0.f;
#pragma unroll
            for (int k = 0; k < 8; k++) {
                int i = base + k;
                i = i < 0 ? -i : i;
                i = min(i, 2 * LEN0 - 2 - i);
                float xv = xg[i];
                sl = fmaf(xv, c_dec_lo[k], sl);
                sh = fmaf(xv, c_dec_hi[k], sh);
            }
            lo[o - bout] = sl;
            hi[o - bout] = sh;
        }
    }
}

// ---- analysis chunk (4 outputs, global chunk index j) from smem (based) ----
__device__ __forceinline__ void analysis_chunk_s(const float* __restrict__ in, int bin, int L,
                                                 float* __restrict__ lo,
                                                 float* __restrict__ hi, int bout, int Lout,
                                                 int j) {
    const int jhi = (L - 8) >> 3;
    if (j >= 1 && j <= jhi) {
        const float4* in4 = reinterpret_cast<const float4*>(in) + ((8 * j - 8 - bin) >> 2);
        float v[16];
#pragma unroll
        for (int q = 0; q < 4; q++) {
            float4 t = in4[q];
            v[4 * q] = t.x; v[4 * q + 1] = t.y; v[4 * q + 2] = t.z; v[4 * q + 3] = t.w;
        }
        float slo[4], shi[4];
#pragma unroll
        for (int m = 0; m < 4; m++) {
            float sl = 0.f, sh = 0.f;
#pragma unroll
            for (int k = 0; k < 8; k++) {
                float xv = v[2 * m + 1 + k];
                sl = fmaf(xv, c_dec_lo[k], sl);
                sh = fmaf(xv, c_dec_hi[k], sh);
            }
            slo[m] = sl; shi[m] = sh;
        }
        int fb = (4 * j - bout) >> 2;
        reinterpret_cast<float4*>(lo)[fb] = make_float4(slo[0], slo[1], slo[2], slo[3]);
        reinterpret_cast<float4*>(hi)[fb] = make_float4(shi[0], shi[1], shi[2], shi[3]);
    } else {
        const int twoLm2 = 2 * L - 2;
#pragma unroll
        for (int m = 0; m < 4; m++) {
            int o = 4 * j + m;
            if (o >= Lout) break;
            int base = 2 * o - 7;
            float sl = 0.f, sh = 0.f;
#pragma unroll
            for (int k = 0; k < 8; k++) {
                int i = base + k;
                i = i < 0 ? -i : i;
                i = min(i, twoLm2 - i);
                float xv = in[i - bin];
                sl = fmaf(xv, c_dec_lo[k], sl);
                sh = fmaf(xv, c_dec_hi[k], sh);
            }
            lo[o - bout] = sl;
            hi[o - bout] = sh;
        }
    }
}

// ---- final stage from 6 local values m[0..5] -> one float4 at out+4f ----
__device__ __forceinline__ void final4(const float m[6],
                                       float e0, float e1, float e2, float e3,
                                       float o0, float o1, float o2, float o3,
                                       float* __restrict__ outg, int f) {
    float r0 = fmaf(e0, m[0], fmaf(e1, m[1], fmaf(e2, m[2], e3 * m[3])));
    float r1 = fmaf(o0, m[1], fmaf(o1, m[2], fmaf(o2, m[3], o3 * m[4])));
    float r2 = fmaf(e0, m[1], fmaf(e1, m[2], fmaf(e2, m[3], e3 * m[4])));
    float r3 = fmaf(o0, m[2], fmaf(o1, m[3], fmaf(o2, m[4], o3 * m[5])));
    reinterpret_cast<float4*>(outg)[f] = make_float4(r0, r1, r2, r3);
}

// ---- band3: single-stage synth, one float4 per thread (f global, 0..2047) ----
// out[4f..4f+3] needs a[2f..2f+5].
__device__ __forceinline__ void synth1_f4(const float* __restrict__ a, int bin,
                                          float e0, float e1, float e2, float e3,
                                          float o0, float o1, float o2, float o3,
                                          float* __restrict__ outg, int f) {
    const float2* a2 = reinterpret_cast<const float2*>(a) + ((2 * f - bin) >> 1);
    float2 A = a2[0], B = a2[1], C = a2[2];
    float m[6] = {A.x, A.y, B.x, B.y, C.x, C.y};
    final4(m, e0, e1, e2, e3, o0, o1, o2, o3, outg, f);
}

// ---- band2: double-fused, one float4 per thread ----
// mid[2f..2f+5] from b[f..f+6] (hi taps), then lo taps to out[4f..4f+3].
__device__ __forceinline__ void synth2_f4(const float* __restrict__ b, int bin,
                                          float a0, float a1, float a2, float a3,
                                          float p0, float p1, float p2, float p3,
                                          float e0, float e1, float e2, float e3,
                                          float o0, float o1, float o2, float o3,
                                          float* __restrict__ outg, int f) {
    float bL[7];
    const float* bp = b + (f - bin);
#pragma unroll
    for (int q = 0; q < 7; q++) bL[q] = bp[q];
    float m[6];
#pragma unroll
    for (int s = 0; s < 6; s += 2) {
        int v = s >> 1;
        m[s]     = fmaf(a0, bL[v],     fmaf(a1, bL[v + 1], fmaf(a2, bL[v + 2], a3 * bL[v + 3])));
        m[s + 1] = fmaf(p0, bL[v + 1], fmaf(p1, bL[v + 2], fmaf(p2, bL[v + 3], p3 * bL[v + 4])));
    }
    final4(m, e0, e1, e2, e3, o0, o1, o2, o3, outg, f);
}

// ---- bands 1/0: triple-fused, one float4 per thread ----
// b(1031-level) ->wA-> 2054 ->lo-> 4100 ->lo-> 8192.
// m1[f..f+6] from b[f>>1 .. (f>>1)+7]; m2[2f..2f+5]; out[4f..4f+3].
__device__ __forceinline__ void synth3_f4(const float* __restrict__ b, int bin,
                                          float a0, float a1, float a2, float a3,
                                          float p0, float p1, float p2, float p3,
                                          float e0, float e1, float e2, float e3,
                                          float o0, float o1, float o2, float o3,
                                          float* __restrict__ outg, int f) {
    const int g = f >> 1;
    float bL[8];
    const float* bp = b + (g - bin);
#pragma unroll
    for (int q = 0; q < 8; q++) bL[q] = bp[q];
    float m1[7];
    if ((f & 1) == 0) {
        // local i even -> global even (uses bL[i/2 .. +3] even taps)
#pragma unroll
        for (int i = 0; i < 7; i++) {
            int v = i >> 1;
            if ((i & 1) == 0)
                m1[i] = fmaf(a0, bL[v],     fmaf(a1, bL[v + 1], fmaf(a2, bL[v + 2], a3 * bL[v + 3])));
            else
                m1[i] = fmaf(p0, bL[v + 1], fmaf(p1, bL[v + 2], fmaf(p2, bL[v + 3], p3 * bL[v + 4])));
        }
    } else {
        // local i even -> global odd
#pragma unroll
        for (int i = 0; i < 7; i++) {
            if ((i & 1) == 0) {
                int v = i >> 1;
                m1[i] = fmaf(p0, bL[v + 1], fmaf(p1, bL[v + 2], fmaf(p2, bL[v + 3], p3 * bL[v + 4])));
            } else {
                int v = (i + 1) >> 1;
                m1[i] = fmaf(a0, bL[v],     fmaf(a1, bL[v + 1], fmaf(a2, bL[v + 2], a3 * bL[v + 3])));
            }
        }
    }
    float m2[6];
#pragma unroll
    for (int s = 0; s < 6; s += 2) {
        int w = s >> 1;
        m2[s]     = fmaf(e0, m1[w],     fmaf(e1, m1[w + 1], fmaf(e2, m1[w + 2], e3 * m1[w + 3])));
        m2[s + 1] = fmaf(o0, m1[w + 1], fmaf(o1, m1[w + 2], fmaf(o2, m1[w + 3], o3 * m1[w + 4])));
    }
    final4(m2, e0, e1, e2, e3, o0, o1, o2, o3, outg, f);
}

__global__ void __launch_bounds__(NT, 6)
dwt_frontend_kernel(const float* __restrict__ x, float* __restrict__ out) {
    extern __shared__ float s[];
    const int tid = threadIdx.x;
    const int half = blockIdx.x & 1;
    const int row = blockIdx.x >> 1;
    const float* xg = x + (size_t)row * LEN0;
    const size_t bstride = (size_t)NROWS * LEN0;
    float* ob = out + (size_t)row * LEN0;

    const int B1 = half ? 2024 : 0;   // A1/D1 covers [B1, B1+2080)
    const int B2 = half ? 1016 : 0;   // A2/D2 covers [B2, B2+1048)
    const int B3 = half ? 512  : 0;   // A3/D3 covers [B3, B3+528)
    const int F4 = half ? 1024 : 0;   // float4-chunk base per half

    // hoisted taps
    const float le0 = c_lo_e[0], le1 = c_lo_e[1], le2 = c_lo_e[2], le3 = c_lo_e[3];
    const float lo0 = c_lo_o[0], lo1 = c_lo_o[1], lo2 = c_lo_o[2], lo3 = c_lo_o[3];
    const float he0 = c_hi_e[0], he1 = c_hi_e[1], he2 = c_hi_e[2], he3 = c_hi_e[3];
    const float ho0 = c_hi_o[0], ho1 = c_hi_o[1], ho2 = c_hi_o[2], ho3 = c_hi_o[3];

    // ---- Ph1: analysis L1 from gmem ----
    {
        const int j0 = half ? 506 : 0;
        const int n  = half ? 519 : 520;
        for (int t = tid; t < n; t += NT)
            analysis_chunk_g(xg, s + OFF_A1, s + OFF_D1, j0 + t, B1);
    }
    __syncthreads();

    // ---- Ph2: analysis L2 (260 chunks) + band3 synth (1024 f4) ----
    {
        const int j0a = half ? 254 : 0;
        float* ob3 = ob + 3 * bstride;
        for (int t = tid; t < 1284; t += NT) {
            if (t < 260)
                analysis_chunk_s(s + OFF_A1, B1, LEN1, s + OFF_A2, s + OFF_D2, B2, LEN2, j0a + t);
            else
                synth1_f4(s + OFF_D1, B1, he0, he1, he2, he3, ho0, ho1, ho2, ho3,
                          ob3, F4 + (t - 260));
        }
    }
    __syncthreads();

    // ---- Ph3: analysis L3 (130 chunks) + band2 synth (1024 f4) ----
    {
        const int j0a = half ? 128 : 0;
        float* ob2 = ob + 2 * bstride;
        for (int t = tid; t < 1154; t += NT) {
            if (t < 130)
                analysis_chunk_s(s + OFF_A2, B2, LEN2, s + OFF_A3, s + OFF_D3, B3, LEN3, j0a + t);
            else
                synth2_f4(s + OFF_D2, B2, he0, he1, he2, he3, ho0, ho1, ho2, ho3,
                          le0, le1, le2, le3, lo0, lo1, lo2, lo3,
                          ob2, F4 + (t - 130));
        }
    }
    __syncthreads();

    // ---- Ph4: bands 1 and 0, triple-fused (1024 + 1024 f4) ----
    {
        float* ob1 = ob + 1 * bstride;
        for (int t = tid; t < 2048; t += NT) {
            if (t < 1024)
                synth3_f4(s + OFF_D3, B3, he0, he1, he2, he3, ho0, ho1, ho2, ho3,
                          le0, le1, le2, le3, lo0, lo1, lo2, lo3,
                          ob1, F4 + t);
            else
                synth3_f4(s + OFF_A3, B3, le0, le1, le2, le3, lo0, lo1, lo2, lo3,
                          le0, le1, le2, le3, lo0, lo1, lo2, lo3,
                          ob, F4 + (t - 1024));
        }
    }
}

extern "C" void kernel_launch(void* const* d_in, const int* in_sizes, int n_in,
                              void* d_out, int out_size) {
    const float* x = (const float*)d_in[0];
    float* out = (float*)d_out;
    const size_t smem = (size_t)ARENA * sizeof(float);   // 25024 B
    cudaFuncSetAttribute(dwt_frontend_kernel,
                         cudaFuncAttributeMaxDynamicSharedMemorySize, (int)smem);
    dwt_frontend_kernel<<<2 * NROWS, NT, smem>>>(x, out);
}

// round 16
// speedup vs baseline: 1.4207x; 1.1581x over previous
#include <cuda_runtime.h>

// 3-level db4 wavelet front-end. R9: composite synthesis filters.
// Each band is ONE transpose-convolution with a compile-time-composed filter:
//   band3: 8 taps, stride 2   band2: 22 taps, stride 4   bands1/0: 50 taps, stride 8
// All taps are immediates (constexpr tables -> FFMA-imm). No divergence, no
// intermediate synthesis buffers. Row split across two 256-thread CTAs.

#define NT 256
#define NROWS 2048
#define LEN0 8192
#define LEN1 4100
#define LEN2 2054
#define LEN3 1031

// ---- per-CTA smem buffers (floats) ----
// A1[0,2080) D1[2080,4160) A2[4160,5208) D2[5208,6256)
// After Ph2, D1 reused: A3[2080,2608) D3[2608,3136)  (A3/D3 16 banks apart)
#define OFF_A1 0
#define OFF_D1 2080
#define OFF_A3 2080
#define OFF_D3 2608
#define OFF_A2 4160
#define OFF_D2 5208
#define ARENA  6256

// ---------------- compile-time composite filters ----------------
struct C22 { float v[22]; };
struct C50 { float v[50]; };

__host__ __device__ constexpr C22 make_c2() {
    const float LO[8] = {0.2303778133f, 0.7148465706f, 0.6308807679f, -0.0279837694f,
                         -0.1870348117f, 0.0308413818f, 0.0328830117f, -0.0105974018f};
    const float HI[8] = {-0.0105974018f, -0.0328830117f, 0.0308413818f, 0.1870348117f,
                         -0.0279837694f, -0.6308807679f, 0.7148465706f, -0.2303778133f};
    C22 c{};
    for (int kp = 0; kp < 8; kp++)
        for (int kq = 0; kq < 8; kq++)
            c.v[kp + 2 * kq] += LO[kp] * HI[kq];
    return c;
}
__host__ __device__ constexpr C50 make_c3(bool hi) {
    const float LO[8] = {0.2303778133f, 0.7148465706f, 0.6308807679f, -0.0279837694f,
                         -0.1870348117f, 0.0308413818f, 0.0328830117f, -0.0105974018f};
    const float HI[8] = {-0.0105974018f, -0.0328830117f, 0.0308413818f, 0.1870348117f,
                         -0.0279837694f, -0.6308807679f, 0.7148465706f, -0.2303778133f};
    C50 c{};
    for (int kp = 0; kp < 8; kp++)
        for (int kq = 0; kq < 8; kq++)
            for (int kz = 0; kz < 8; kz++)
                c.v[kp + 2 * kq + 4 * kz] += LO[kp] * LO[kq] * (hi ? HI[kz] : LO[kz]);
    return c;
}
__device__ const C22 C2H = make_c2();
__device__ const C50 C3H = make_c3(true);   // band1: hi at coarsest stage
__device__ const C50 C3L = make_c3(false);  // band0: lo everywhere

// ---------------- analysis: stride-2 correlation, reflect pad 7 ----------------
__device__ __forceinline__ void analysis_chunk_g(const float* __restrict__ xg,
                                                 float* __restrict__ lo,
                                                 float* __restrict__ hi,
                                                 int j, int bout) {
    const float DLO[8] = {-0.0105974018f, 0.0328830117f, 0.0308413818f, -0.1870348117f,
                          -0.0279837694f, 0.6308807679f, 0.7148465706f, 0.2303778133f};
    const float DHI[8] = {-0.2303778133f, 0.7148465706f, -0.6308807679f, -0.0279837694f,
                          0.1870348117f, 0.0308413818f, -0.0328830117f, -0.0105974018f};
    if (j >= 1 && j <= 1023) {
        const float4* in4 = reinterpret_cast<const float4*>(xg) + (2 * j - 2);
        float v[16];
#pragma unroll
        for (int q = 0; q < 4; q++) {
            float4 t = in4[q];
            v[4 * q] = t.x; v[4 * q + 1] = t.y; v[4 * q + 2] = t.z; v[4 * q + 3] = t.w;
        }
        float slo[4], shi[4];
#pragma unroll
        for (int m = 0; m < 4; m++) {
            float sl = 0.f, sh = 0.f;
#pragma unroll
            for (int k = 0; k < 8; k++) {
                float xv = v[2 * m + 1 + k];
                sl = fmaf(xv, DLO[k], sl);
                sh = fmaf(xv, DHI[k], sh);
            }
            slo[m] = sl; shi[m] = sh;
        }
        int fb = (4 * j - bout) >> 2;
        reinterpret_cast<float4*>(lo)[fb] = make_float4(slo[0], slo[1], slo[2], slo[3]);
        reinterpret_cast<float4*>(hi)[fb] = make_float4(shi[0], shi[1], shi[2], shi[3]);
    } else {
#pragma unroll
        for (int m = 0; m < 4; m++) {
            int o = 4 * j + m;
            if (o >= LEN1) break;
            int base = 2 * o - 7;
            float sl = 0.f, sh = 0.f;
#pragma unroll
            for (int k = 0; k < 8; k++) {
                int i = base + k;
                i = i < 0 ? -i : i;
                i = min(i, 2 * LEN0 - 2 - i);
                float xv = xg[i];
                sl = fmaf(xv, DLO[k], sl);
                sh = fmaf(xv, DHI[k], sh);
            }
            lo[o - bout] = sl;
            hi[o - bout] = sh;
        }
    }
}

__device__ __forceinline__ void analysis_chunk_s(const float* __restrict__ in, int bin, int L,
                                                 float* __restrict__ lo,
                                                 float* __restrict__ hi, int bout, int Lout,
                                                 int j) {
    const float DLO[8] = {-0.0105974018f, 0.0328830117f, 0.0308413818f, -0.1870348117f,
                          -0.0279837694f, 0.6308807679f, 0.7148465706f, 0.2303778133f};
    const float DHI[8] = {-0.2303778133f, 0.7148465706f, -0.6308807679f, -0.0279837694f,
                          0.1870348117f, 0.0308413818f, -0.0328830117f, -0.0105974018f};
    const int jhi = (L - 8) >> 3;
    if (j >= 1 && j <= jhi) {
        const float4* in4 = reinterpret_cast<const float4*>(in) + ((8 * j - 8 - bin) >> 2);
        float v[16];
#pragma unroll
        for (int q = 0; q < 4; q++) {
            float4 t = in4[q];
            v[4 * q] = t.x; v[4 * q + 1] = t.y; v[4 * q + 2] = t.z; v[4 * q + 3] = t.w;
        }
        float slo[4], shi[4];
#pragma unroll
        for (int m = 0; m < 4; m++) {
            float sl = 0.f, sh = 0.f;
#pragma unroll
            for (int k = 0; k < 8; k++) {
                float xv = v[2 * m + 1 + k];
                sl = fmaf(xv, DLO[k], sl);
                sh = fmaf(xv, DHI[k], sh);
            }
            slo[m] = sl; shi[m] = sh;
        }
        int fb = (4 * j - bout) >> 2;
        reinterpret_cast<float4*>(lo)[fb] = make_float4(slo[0], slo[1], slo[2], slo[3]);
        reinterpret_cast<float4*>(hi)[fb] = make_float4(shi[0], shi[1], shi[2], shi[3]);
    } else {
        const int twoLm2 = 2 * L - 2;
#pragma unroll
        for (int m = 0; m < 4; m++) {
            int o = 4 * j + m;
            if (o >= Lout) break;
            int base = 2 * o - 7;
            float sl = 0.f, sh = 0.f;
#pragma unroll
            for (int k = 0; k < 8; k++) {
                int i = base + k;
                i = i < 0 ? -i : i;
                i = min(i, twoLm2 - i);
                float xv = in[i - bin];
                sl = fmaf(xv, DLO[k], sl);
                sh = fmaf(xv, DHI[k], sh);
            }
            lo[o - bout] = sl;
            hi[o - bout] = sh;
        }
    }
}

// ---- band3: single-stage REC_HI, out[4f+r] = sum_d D1[2f+d]*W[7+r-2d] ----
__device__ __forceinline__ void ph2_unit(const float* __restrict__ sD1, int B1,
                                         int f, float* __restrict__ og) {
    const float W[8] = {-0.0105974018f, -0.0328830117f, 0.0308413818f, 0.1870348117f,
                        -0.0279837694f, -0.6308807679f, 0.7148465706f, -0.2303778133f};
    const float2* p = reinterpret_cast<const float2*>(sD1 + (2 * f - B1));
    float2 A = p[0], B = p[1], C = p[2];
    float bl[6] = {A.x, A.y, B.x, B.y, C.x, C.y};
    float a[4] = {0.f, 0.f, 0.f, 0.f};
#pragma unroll
    for (int d = 0; d < 6; d++)
#pragma unroll
        for (int r = 0; r < 4; r++) {
            const int i = 7 + r - 2 * d;
            if (i >= 0 && i <= 7) a[r] = fmaf(W[i], bl[d], a[r]);
        }
    reinterpret_cast<float4*>(og)[f] = make_float4(a[0], a[1], a[2], a[3]);
}

// ---- band2: 22-tap composite, out[4f+r] = sum_d D2[f+d]*C2[21+r-4d] ----
__device__ __forceinline__ void ph3_unit(const float* __restrict__ sD2, int B2,
                                         int f, float* __restrict__ og) {
    float bl[7];
#pragma unroll
    for (int d = 0; d < 7; d++) bl[d] = sD2[f + d - B2];
    float a[4] = {0.f, 0.f, 0.f, 0.f};
#pragma unroll
    for (int d = 0; d < 7; d++)
#pragma unroll
        for (int r = 0; r < 4; r++) {
            const int i = 21 + r - 4 * d;
            if (i >= 0 && i <= 21) a[r] = fmaf(C2H.v[i], bl[d], a[r]);
        }
    reinterpret_cast<float4*>(og)[f] = make_float4(a[0], a[1], a[2], a[3]);
}

// ---- bands 1/0: 50-tap composite, out[8g+r] = sum_d b[g+d]*C3[49+r-8d] ----
template <bool HI>
__device__ __forceinline__ void ph4_unit(const float* __restrict__ src, int bin,
                                         int g, float* __restrict__ og) {
    float bl[8];
#pragma unroll
    for (int d = 0; d < 8; d++) bl[d] = src[g + d - bin];
    float a[8] = {0.f, 0.f, 0.f, 0.f, 0.f, 0.f, 0.f, 0.f};
#pragma unroll
    for (int d = 0; d < 8; d++)
#pragma unroll
        for (int r = 0; r < 8; r++) {
            const int i = 49 + r - 8 * d;
            if (i >= 0 && i <= 49)
                a[r] = fmaf(HI ? C3H.v[i] : C3L.v[i], bl[d], a[r]);
        }
    float4* o4 = reinterpret_cast<float4*>(og);
    o4[2 * g]     = make_float4(a[0], a[1], a[2], a[3]);
    o4[2 * g + 1] = make_float4(a[4], a[5], a[6], a[7]);
}

__global__ void __launch_bounds__(NT, 6)
dwt_frontend_kernel(const float* __restrict__ x, float* __restrict__ out) {
    extern __shared__ float s[];
    const int tid = threadIdx.x;
    const int half = blockIdx.x & 1;
    const int row = blockIdx.x >> 1;
    const float* xg = x + (size_t)row * LEN0;
    const size_t bstride = (size_t)NROWS * LEN0;
    float* ob = out + (size_t)row * LEN0;

    const int B1 = half ? 2024 : 0;   // A1/D1 covers [B1, B1+2080)
    const int B2 = half ? 1016 : 0;   // A2/D2 covers [B2, B2+1048)
    const int B3 = half ? 512  : 0;   // A3/D3 covers [B3, B3+528)
    const int F4 = half ? 1024 : 0;   // float4 base per half

    // ---- Ph1: analysis L1 from gmem ----
    {
        const int j0 = half ? 506 : 0;
        const int n  = half ? 519 : 520;
        for (int t = tid; t < n; t += NT)
            analysis_chunk_g(xg, s + OFF_A1, s + OFF_D1, j0 + t, B1);
    }
    __syncthreads();

    // ---- Ph2: analysis L2 (260 chunks) + band3 (1024 f4) ----
    {
        const int j0a = half ? 254 : 0;
        float* ob3 = ob + 3 * bstride;
        for (int t = tid; t < 1284; t += NT) {
            if (t < 260)
                analysis_chunk_s(s + OFF_A1, B1, LEN1, s + OFF_A2, s + OFF_D2, B2, LEN2, j0a + t);
            else
                ph2_unit(s + OFF_D1, B1, F4 + (t - 260), ob3);
        }
    }
    __syncthreads();

    // ---- Ph3: analysis L3 (130 chunks) + band2 composite (1024 f4) ----
    {
        const int j0a = half ? 128 : 0;
        float* ob2 = ob + 2 * bstride;
        for (int t = tid; t < 1154; t += NT) {
            if (t < 130)
                analysis_chunk_s(s + OFF_A2, B2, LEN2, s + OFF_A3, s + OFF_D3, B3, LEN3, j0a + t);
            else
                ph3_unit(s + OFF_D2, B2, F4 + (t - 130), ob2);
        }
    }
    __syncthreads();

    // ---- Ph4: bands 1 and 0, 50-tap composite (512 + 512 period-units) ----
    {
        float* ob1 = ob + 1 * bstride;
        const int G0 = F4 >> 1;
        for (int t = tid; t < 1024; t += NT) {   // band uniform per k-iteration
            if (t < 512)
                ph4_unit<true>(s + OFF_D3, B3, G0 + t, ob1);
            else
                ph4_unit<false>(s + OFF_A3, B3, G0 + (t - 512), ob);
        }
    }
}

extern "C" void kernel_launch(void* const* d_in, const int* in_sizes, int n_in,
                              void* d_out, int out_size) {
    const float* x = (const float*)d_in[0];
    float* out = (float*)d_out;
    const size_t smem = (size_t)ARENA * sizeof(float);   // 25024 B
    cudaFuncSetAttribute(dwt_frontend_kernel,
                         cudaFuncAttributeMaxDynamicSharedMemorySize, (int)smem);
    dwt_frontend_kernel<<<2 * NROWS, NT, smem>>>(x, out);
}

// round 17
// speedup vs baseline: 1.4461x; 1.0179x over previous
#include <cuda_runtime.h>

// 3-level db4 wavelet front-end. R10: R9 base (composite synthesis filters,
// row split across two 256-thread CTAs) + streaming stores (st.global.cs)
// for all band outputs + relaxed launch bounds for 8-CTA residency.

#define NT 256
#define NROWS 2048
#define LEN0 8192
#define LEN1 4100
#define LEN2 2054
#define LEN3 1031

// ---- per-CTA smem buffers (floats) ----
// A1[0,2080) D1[2080,4160) A2[4160,5208) D2[5208,6256)
// After Ph2, D1 reused: A3[2080,2608) D3[2608,3136)
#define OFF_A1 0
#define OFF_D1 2080
#define OFF_A3 2080
#define OFF_D3 2608
#define OFF_A2 4160
#define OFF_D2 5208
#define ARENA  6256

// streaming 128-bit store: evict-first, output is never re-read
__device__ __forceinline__ void stcs4(float4* p, float4 v) {
    asm volatile("st.global.cs.v4.f32 [%0], {%1, %2, %3, %4};"
                 :: "l"(p), "f"(v.x), "f"(v.y), "f"(v.z), "f"(v.w) : "memory");
}

// ---------------- compile-time composite filters ----------------
struct C22 { float v[22]; };
struct C50 { float v[50]; };

__host__ __device__ constexpr C22 make_c2() {
    const float LO[8] = {0.2303778133f, 0.7148465706f, 0.6308807679f, -0.0279837694f,
                         -0.1870348117f, 0.0308413818f, 0.0328830117f, -0.0105974018f};
    const float HI[8] = {-0.0105974018f, -0.0328830117f, 0.0308413818f, 0.1870348117f,
                         -0.0279837694f, -0.6308807679f, 0.7148465706f, -0.2303778133f};
    C22 c{};
    for (int kp = 0; kp < 8; kp++)
        for (int kq = 0; kq < 8; kq++)
            c.v[kp + 2 * kq] += LO[kp] * HI[kq];
    return c;
}
__host__ __device__ constexpr C50 make_c3(bool hi) {
    const float LO[8] = {0.2303778133f, 0.7148465706f, 0.6308807679f, -0.0279837694f,
                         -0.1870348117f, 0.0308413818f, 0.0328830117f, -0.0105974018f};
    const float HI[8] = {-0.0105974018f, -0.0328830117f, 0.0308413818f, 0.1870348117f,
                         -0.0279837694f, -0.6308807679f, 0.7148465706f, -0.2303778133f};
    C50 c{};
    for (int kp = 0; kp < 8; kp++)
        for (int kq = 0; kq < 8; kq++)
            for (int kz = 0; kz < 8; kz++)
                c.v[kp + 2 * kq + 4 * kz] += LO[kp] * LO[kq] * (hi ? HI[kz] : LO[kz]);
    return c;
}
__device__ const C22 C2H = make_c2();
__device__ const C50 C3H = make_c3(true);   // band1: hi at coarsest stage
__device__ const C50 C3L = make_c3(false);  // band0: lo everywhere

// ---------------- analysis: stride-2 correlation, reflect pad 7 ----------------
__device__ __forceinline__ void analysis_chunk_g(const float* __restrict__ xg,
                                                 float* __restrict__ lo,
                                                 float* __restrict__ hi,
                                                 int j, int bout) {
    const float DLO[8] = {-0.0105974018f, 0.0328830117f, 0.0308413818f, -0.1870348117f,
                          -0.0279837694f, 0.6308807679f, 0.7148465706f, 0.2303778133f};
    const float DHI[8] = {-0.2303778133f, 0.7148465706f, -0.6308807679f, -0.0279837694f,
                          0.1870348117f, 0.0308413818f, -0.0328830117f, -0.0105974018f};
    if (j >= 1 && j <= 1023) {
        const float4* in4 = reinterpret_cast<const float4*>(xg) + (2 * j - 2);
        float v[16];
#pragma unroll
        for (int q = 0; q < 4; q++) {
            float4 t = in4[q];
            v[4 * q] = t.x; v[4 * q + 1] = t.y; v[4 * q + 2] = t.z; v[4 * q + 3] = t.w;
        }
        float slo[4], shi[4];
#pragma unroll
        for (int m = 0; m < 4; m++) {
            float sl = 0.f, sh = 0.f;
#pragma unroll
            for (int k = 0; k < 8; k++) {
                float xv = v[2 * m + 1 + k];
                sl = fmaf(xv, DLO[k], sl);
                sh = fmaf(xv, DHI[k], sh);
            }
            slo[m] = sl; shi[m] = sh;
        }
        int fb = (4 * j - bout) >> 2;
        reinterpret_cast<float4*>(lo)[fb] = make_float4(slo[0], slo[1], slo[2], slo[3]);
        reinterpret_cast<float4*>(hi)[fb] = make_float4(shi[0], shi[1], shi[2], shi[3]);
    } else {
#pragma unroll
        for (int m = 0; m < 4; m++) {
            int o = 4 * j + m;
            if (o >= LEN1) break;
            int base = 2 * o - 7;
            float sl = 0.f, sh = 0.f;
#pragma unroll
            for (int k = 0; k < 8; k++) {
                int i = base + k;
                i = i < 0 ? -i : i;
                i = min(i, 2 * LEN0 - 2 - i);
                float xv = xg[i];
                sl = fmaf(xv, DLO[k], sl);
                sh = fmaf(xv, DHI[k], sh);
            }
            lo[o - bout] = sl;
            hi[o - bout] = sh;
        }
    }
}

__device__ __forceinline__ void analysis_chunk_s(const float* __restrict__ in, int bin, int L,
                                                 float* __restrict__ lo,
                                                 float* __restrict__ hi, int bout, int Lout,
                                                 int j) {
    const float DLO[8] = {-0.0105974018f, 0.0328830117f, 0.0308413818f, -0.1870348117f,
                          -0.0279837694f, 0.6308807679f, 0.7148465706f, 0.2303778133f};
    const float DHI[8] = {-0.2303778133f, 0.7148465706f, -0.6308807679f, -0.0279837694f,
                          0.1870348117f, 0.0308413818f, -0.0328830117f, -0.0105974018f};
    const int jhi = (L - 8) >> 3;
    if (j >= 1 && j <= jhi) {
        const float4* in4 = reinterpret_cast<const float4*>(in) + ((8 * j - 8 - bin) >> 2);
        float v[16];
#pragma unroll
        for (int q = 0; q < 4; q++) {
            float4 t = in4[q];
            v[4 * q] = t.x; v[4 * q + 1] = t.y; v[4 * q + 2] = t.z; v[4 * q + 3] = t.w;
        }
        float slo[4], shi[4];
#pragma unroll
        for (int m = 0; m < 4; m++) {
            float sl = 0.f, sh = 0.f;
#pragma unroll
            for (int k = 0; k < 8; k++) {
                float xv = v[2 * m + 1 + k];
                sl = fmaf(xv, DLO[k], sl);
                sh = fmaf(xv, DHI[k], sh);
            }
            slo[m] = sl; shi[m] = sh;
        }
        int fb = (4 * j - bout) >> 2;
        reinterpret_cast<float4*>(lo)[fb] = make_float4(slo[0], slo[1], slo[2], slo[3]);
        reinterpret_cast<float4*>(hi)[fb] = make_float4(shi[0], shi[1], shi[2], shi[3]);
    } else {
        const int twoLm2 = 2 * L - 2;
#pragma unroll
        for (int m = 0; m < 4; m++) {
            int o = 4 * j + m;
            if (o >= Lout) break;
            int base = 2 * o - 7;
            float sl = 0.f, sh = 0.f;
#pragma unroll
            for (int k = 0; k < 8; k++) {
                int i = base + k;
                i = i < 0 ? -i : i;
                i = min(i, twoLm2 - i);
                float xv = in[i - bin];
                sl = fmaf(xv, DLO[k], sl);
                sh = fmaf(xv, DHI[k], sh);
            }
            lo[o - bout] = sl;
            hi[o - bout] = sh;
        }
    }
}

// ---- band3: single-stage REC_HI, out[4f+r] = sum_d D1[2f+d]*W[7+r-2d] ----
__device__ __forceinline__ void ph2_unit(const float* __restrict__ sD1, int B1,
                                         int f, float* __restrict__ og) {
    const float W[8] = {-0.0105974018f, -0.0328830117f, 0.0308413818f, 0.1870348117f,
                        -0.0279837694f, -0.6308807679f, 0.7148465706f, -0.2303778133f};
    const float2* p = reinterpret_cast<const float2*>(sD1 + (2 * f - B1));
    float2 A = p[0], B = p[1], C = p[2];
    float bl[6] = {A.x, A.y, B.x, B.y, C.x, C.y};
    float a[4] = {0.f, 0.f, 0.f, 0.f};
#pragma unroll
    for (int d = 0; d < 6; d++)
#pragma unroll
        for (int r = 0; r < 4; r++) {
            const int i = 7 + r - 2 * d;
            if (i >= 0 && i <= 7) a[r] = fmaf(W[i], bl[d], a[r]);
        }
    stcs4(reinterpret_cast<float4*>(og) + f, make_float4(a[0], a[1], a[2], a[3]));
}

// ---- band2: 22-tap composite, out[4f+r] = sum_d D2[f+d]*C2[21+r-4d] ----
__device__ __forceinline__ void ph3_unit(const float* __restrict__ sD2, int B2,
                                         int f, float* __restrict__ og) {
    float bl[7];
#pragma unroll
    for (int d = 0; d < 7; d++) bl[d] = sD2[f + d - B2];
    float a[4] = {0.f, 0.f, 0.f, 0.f};
#pragma unroll
    for (int d = 0; d < 7; d++)
#pragma unroll
        for (int r = 0; r < 4; r++) {
            const int i = 21 + r - 4 * d;
            if (i >= 0 && i <= 21) a[r] = fmaf(C2H.v[i], bl[d], a[r]);
        }
    stcs4(reinterpret_cast<float4*>(og) + f, make_float4(a[0], a[1], a[2], a[3]));
}

// ---- bands 1/0: 50-tap composite, out[8g+r] = sum_d b[g+d]*C3[49+r-8d] ----
template <bool HI>
__device__ __forceinline__ void ph4_unit(const float* __restrict__ src, int bin,
                                         int g, float* __restrict__ og) {
    float bl[8];
#pragma unroll
    for (int d = 0; d < 8; d++) bl[d] = src[g + d - bin];
    float a[8] = {0.f, 0.f, 0.f, 0.f, 0.f, 0.f, 0.f, 0.f};
#pragma unroll
    for (int d = 0; d < 8; d++)
#pragma unroll
        for (int r = 0; r < 8; r++) {
            const int i = 49 + r - 8 * d;
            if (i >= 0 && i <= 49)
                a[r] = fmaf(HI ? C3H.v[i] : C3L.v[i], bl[d], a[r]);
        }
    float4* o4 = reinterpret_cast<float4*>(og);
    stcs4(o4 + 2 * g,     make_float4(a[0], a[1], a[2], a[3]));
    stcs4(o4 + 2 * g + 1, make_float4(a[4], a[5], a[6], a[7]));
}

__global__ void __launch_bounds__(NT)
dwt_frontend_kernel(const float* __restrict__ x, float* __restrict__ out) {
    extern __shared__ float s[];
    const int tid = threadIdx.x;
    const int half = blockIdx.x & 1;
    const int row = blockIdx.x >> 1;
    const float* xg = x + (size_t)row * LEN0;
    const size_t bstride = (size_t)NROWS * LEN0;
    float* ob = out + (size_t)row * LEN0;
    float* ob1 = ob + 1 * bstride;
    float* ob2 = ob + 2 * bstride;
    float* ob3 = ob + 3 * bstride;

    const int B1 = half ? 2024 : 0;   // A1/D1 covers [B1, B1+2080)
    const int B2 = half ? 1016 : 0;   // A2/D2 covers [B2, B2+1048)
    const int B3 = half ? 512  : 0;   // A3/D3 covers [B3, B3+528)
    const int F4 = half ? 1024 : 0;   // float4 base per half

    // ---- Ph1: analysis L1 from gmem ----
    {
        const int j0 = half ? 506 : 0;
        const int n  = half ? 519 : 520;
        for (int t = tid; t < n; t += NT)
            analysis_chunk_g(xg, s + OFF_A1, s + OFF_D1, j0 + t, B1);
    }
    __syncthreads();

    // ---- Ph2: analysis L2 (260 chunks) + band3 (1024 f4) ----
    {
        const int j0a = half ? 254 : 0;
        for (int t = tid; t < 1284; t += NT) {
            if (t < 260)
                analysis_chunk_s(s + OFF_A1, B1, LEN1, s + OFF_A2, s + OFF_D2, B2, LEN2, j0a + t);
            else
                ph2_unit(s + OFF_D1, B1, F4 + (t - 260), ob3);
        }
    }
    __syncthreads();

    // ---- Ph3: analysis L3 (130 chunks) + band2 composite (1024 f4) ----
    {
        const int j0a = half ? 128 : 0;
        for (int t = tid; t < 1154; t += NT) {
            if (t < 130)
                analysis_chunk_s(s + OFF_A2, B2, LEN2, s + OFF_A3, s + OFF_D3, B3, LEN3, j0a + t);
            else
                ph3_unit(s + OFF_D2, B2, F4 + (t - 130), ob2);
        }
    }
    __syncthreads();

    // ---- Ph4: bands 1 and 0, 50-tap composite (512 + 512 period-units) ----
    {
        const int G0 = F4 >> 1;
        for (int t = tid; t < 1024; t += NT) {
            if (t < 512)
                ph4_unit<true>(s + OFF_D3, B3, G0 + t, ob1);
            else
                ph4_unit<false>(s + OFF_A3, B3, G0 + (t - 512), ob);
        }
    }
}

extern "C" void kernel_launch(void* const* d_in, const int* in_sizes, int n_in,
                              void* d_out, int out_size) {
    const float* x = (const float*)d_in[0];
    float* out = (float*)d_out;
    const size_t smem = (size_t)ARENA * sizeof(float);   // 25024 B
    cudaFuncSetAttribute(dwt_frontend_kernel,
                         cudaFuncAttributeMaxDynamicSharedMemorySize, (int)smem);
    dwt_frontend_kernel<<<2 * NROWS, NT, smem>>>(x, out);
}